// round 11
// baseline (speedup 1.0000x reference)
#include <cuda_runtime.h>
#include <cuda_fp16.h>
#include <cstdint>
#include <cmath>

constexpr int BATCH = 8;
constexpr int SEQ   = 4096;
constexpr int DIM   = 768;
constexpr int NST   = 16;
constexpr int ROWS  = BATCH * SEQ;        // 32768
constexpr int CHUNK = 32;
constexpr int NCHUNK = SEQ / CHUNK;       // 128
constexpr int NTASK  = BATCH * NCHUNK;    // 1024

__device__ float  d_gu[ROWS * NST];
__device__ float  d_lend[NTASK * NST];
__device__ float  d_hstart[NTASK * NST];
__device__ float  d_Ppow[CHUNK * NST * NST];   // Ppow[j] = T^(j+1) (fp32)
__device__ __half d_pph[CHUNK * NST * NST];    // same, fp16 (for in-gemm2 fixup)
__device__ float  d_Qsq[7 * NST * NST];        // Qsq[t] = (T^C)^(2^t)
__device__ __half d_xh[ROWS * DIM];            // fp16 x (written by gemm1)
__device__ __half d_wsk[DIM * DIM];            // fp16 W_skip
__device__ __half d_woh[DIM * NST];            // fp16 W_out
__device__ int    d_cnt_local;
__device__ int    d_cnt_mid;

#define DEVI __device__ __forceinline__

DEVI uint32_t smem_u32(const void* p) {
    uint32_t a;
    asm("{ .reg .u64 t; cvta.to.shared.u64 t, %1; cvt.u32.u64 %0, t; }" : "=r"(a) : "l"(p));
    return a;
}
DEVI void cpa16(uint32_t dst, const void* src) {
    asm volatile("cp.async.ca.shared.global [%0], [%1], 16;" :: "r"(dst), "l"(src));
}
DEVI void cpa_commit() { asm volatile("cp.async.commit_group;"); }
DEVI void cpa_wait2()  { asm volatile("cp.async.wait_group 2;"); }
DEVI void ldm4(uint32_t* r, uint32_t a) {
    asm volatile("ldmatrix.sync.aligned.m8n8.x4.shared.b16 {%0,%1,%2,%3}, [%4];"
                 : "=r"(r[0]), "=r"(r[1]), "=r"(r[2]), "=r"(r[3]) : "r"(a));
}
DEVI void mma16816(float* c, const uint32_t* a, uint32_t b0, uint32_t b1) {
    asm volatile(
        "mma.sync.aligned.m16n8k16.row.col.f32.f16.f16.f32 "
        "{%0,%1,%2,%3},{%4,%5,%6,%7},{%8,%9},{%0,%1,%2,%3};"
        : "+f"(c[0]), "+f"(c[1]), "+f"(c[2]), "+f"(c[3])
        : "r"(a[0]), "r"(a[1]), "r"(a[2]), "r"(a[3]), "r"(b0), "r"(b1));
}
DEVI float dot4(float4 a, float4 b) {
    return a.x * b.x + a.y * b.y + a.z * b.z + a.w * b.w;
}

// --------------------------------------------------------------------------
// GEMM1 (+ fused prep): blocks 0..255 compute gu tile; blocks 256.. do prep.
// --------------------------------------------------------------------------
constexpr int G1_BS = 776;
constexpr int G1_B  = 0;                       // 32*776*2 = 49664
constexpr int G1_A  = 49664;                   // 4 * 128*40*2 = 40960
constexpr int G1_BIAS = G1_A + 40960;          // 90624
constexpr int G1TOTAL = G1_BIAS + 128;
constexpr int AST = 40;
constexpr int G1_GEMM_BLKS = 256;
constexpr int G1_PREP_BLKS = 589;              // 1 powers + 576 Wskip + 12 Wout

__global__ void __launch_bounds__(256, 2) k_gemm1(const float* __restrict__ x,
                                                  const float* __restrict__ Win,
                                                  const float* __restrict__ Wgate,
                                                  const float* __restrict__ bin,
                                                  const float* __restrict__ bgate,
                                                  const float* __restrict__ a_logit,
                                                  const float* __restrict__ U,
                                                  const float* __restrict__ V,
                                                  const float* __restrict__ Wskip,
                                                  const float* __restrict__ Wout) {
    int tid = threadIdx.x;
    if (blockIdx.x >= G1_GEMM_BLKS) {
        int pbid = blockIdx.x - G1_GEMM_BLKS;
        if (pbid == 0) {
            if (tid == 0) { d_cnt_local = 0; d_cnt_mid = 0; }
            __shared__ float Ts[256], cur[256];
            int n = tid >> 4, m = tid & 15;
            float acc = 0.f;
#pragma unroll
            for (int r = 0; r < 8; r++) acc += V[m * 8 + r] * U[n * 8 + r];
            if (m == n) acc += 1.f / (1.f + expf(-a_logit[n]));
            Ts[tid] = acc; cur[tid] = acc;
            d_Ppow[tid] = acc; d_pph[tid] = __float2half(acc);
            __syncthreads();
            for (int j = 1; j < CHUNK; j++) {
                float s = 0.f;
#pragma unroll
                for (int q = 0; q < 16; q++) s += Ts[n * 16 + q] * cur[q * 16 + m];
                __syncthreads();
                cur[tid] = s;
                d_Ppow[j * 256 + tid] = s;
                d_pph[j * 256 + tid] = __float2half(s);
                __syncthreads();
            }
            for (int tt = 0; tt < 7; tt++) {
                d_Qsq[tt * 256 + tid] = cur[tid];
                float s = 0.f;
#pragma unroll
                for (int q = 0; q < 16; q++) s += cur[n * 16 + q] * cur[q * 16 + m];
                __syncthreads();
                cur[tid] = s;
                __syncthreads();
            }
        } else if (pbid <= 576) {
            int i = (pbid - 1) * 256 + tid;        // float4 index into Wskip
            float4 v = ((const float4*)Wskip)[i];
            ((__half2*)d_wsk)[2 * i]     = __floats2half2_rn(v.x, v.y);
            ((__half2*)d_wsk)[2 * i + 1] = __floats2half2_rn(v.z, v.w);
        } else {
            int j = (pbid - 577) * 256 + tid;      // float4 index into Wout
            if (j < DIM * NST / 4) {
                float4 v = ((const float4*)Wout)[j];
                ((__half2*)d_woh)[2 * j]     = __floats2half2_rn(v.x, v.y);
                ((__half2*)d_woh)[2 * j + 1] = __floats2half2_rn(v.z, v.w);
            }
        }
        return;
    }

    extern __shared__ char smem[];
    __half* sBh = (__half*)(smem + G1_B);
    __half* sAh = (__half*)(smem + G1_A);
    float*  sb  = (float*)(smem + G1_BIAS);
    int w = tid >> 5, l = tid & 31;
    int mt = blockIdx.x;

    for (int i = tid; i < 6144; i += 256) {
        int row = i / 192, c4 = i % 192;
        const float* src = (row < 16) ? (Win + (size_t)row * DIM) : (Wgate + (size_t)(row - 16) * DIM);
        float4 v = ((const float4*)src)[c4];
        *(__half2*)(sBh + row * G1_BS + c4 * 4)     = __floats2half2_rn(v.x, v.y);
        *(__half2*)(sBh + row * G1_BS + c4 * 4 + 2) = __floats2half2_rn(v.z, v.w);
    }
    if (tid < 16) { sb[tid] = bin[tid]; sb[16 + tid] = bgate[tid]; }

    int arow = tid >> 1, ahalf = tid & 1;
    const float* Abase = x + (size_t)(mt * 128 + arow) * DIM + ahalf * 16;
    __half* xdst = d_xh + (size_t)(mt * 128 + arow) * DIM + ahalf * 16;

    auto convert_store = [&](const float4* rg, int kc) {
        uint32_t hp[8];
#pragma unroll
        for (int q = 0; q < 4; q++) {
            __half2 h0 = __floats2half2_rn(rg[q].x, rg[q].y);
            __half2 h1 = __floats2half2_rn(rg[q].z, rg[q].w);
            hp[2 * q]     = *(uint32_t*)&h0;
            hp[2 * q + 1] = *(uint32_t*)&h1;
        }
        __half* Ad = sAh + (kc & 3) * (128 * AST) + arow * AST + ahalf * 16;
        *(uint4*)Ad       = make_uint4(hp[0], hp[1], hp[2], hp[3]);
        *(uint4*)(Ad + 8) = make_uint4(hp[4], hp[5], hp[6], hp[7]);
        *(uint4*)(xdst + kc * 32)     = make_uint4(hp[0], hp[1], hp[2], hp[3]);
        *(uint4*)(xdst + kc * 32 + 8) = make_uint4(hp[4], hp[5], hp[6], hp[7]);
    };

    float4 rg[4];
#pragma unroll
    for (int q = 0; q < 4; q++) rg[q] = ((const float4*)Abase)[q];
    convert_store(rg, 0);
#pragma unroll
    for (int q = 0; q < 4; q++) rg[q] = ((const float4*)(Abase + 32))[q];

    float c[4][4];
#pragma unroll
    for (int i = 0; i < 4; i++)
#pragma unroll
        for (int j = 0; j < 4; j++) c[i][j] = 0.f;

    uint32_t aAddr = smem_u32(sAh);
    uint32_t bAddr = smem_u32(sBh);

    for (int kc = 0; kc < 24; kc++) {
        __syncthreads();
        if (kc < 23) {
            convert_store(rg, kc + 1);
            if (kc < 22) {
                const float4* nsrc = (const float4*)(Abase + (kc + 2) * 32);
#pragma unroll
                for (int q = 0; q < 4; q++) rg[q] = nsrc[q];
            }
        }
        uint32_t Ab = aAddr + (kc & 3) * (128 * AST * 2);
        uint32_t Bb = bAddr + kc * 32 * 2;
#pragma unroll
        for (int ks = 0; ks < 2; ks++) {
            uint32_t a[4];
            ldm4(a, Ab + ((w * 16 + (l & 15)) * AST + ks * 16 + (l >> 4) * 8) * 2);
            uint32_t bf[2][4];
#pragma unroll
            for (int i = 0; i < 2; i++)
                ldm4(bf[i], Bb + ((i * 16 + (l & 15)) * G1_BS + ks * 16 + (l >> 4) * 8) * 2);
#pragma unroll
            for (int nt = 0; nt < 4; nt++)
                mma16816(c[nt], a, bf[nt >> 1][nt & 1], bf[nt >> 1][(nt & 1) + 2]);
        }
    }

    int g = l >> 2, t2 = (l & 3) * 2;
#pragma unroll
    for (int h = 0; h < 2; h++) {
        int r = mt * 128 + w * 16 + h * 8 + g;
#pragma unroll
        for (int nt = 0; nt < 2; nt++) {
            float v[2];
#pragma unroll
            for (int e = 0; e < 2; e++) {
                int col = nt * 8 + t2 + e;
                float u  = c[nt][2 * h + e] + sb[col];
                float gp = c[nt + 2][2 * h + e] + sb[16 + col];
                v[e] = u / (1.f + expf(-gp));
            }
            *(float2*)(d_gu + (size_t)r * 16 + nt * 8 + t2) = make_float2(v[0], v[1]);
        }
    }
}

// --------------------------------------------------------------------------
// k_main: fused scan + GEMM2.
//  blocks 0..63   : local chunk scans (16 tasks each, in-place on d_gu)
//  blocks 64..71  : Kogge-Stone mid scan (one batch each)
//  blocks 72..    : GEMM2  y = [x | hs] [Wskip | Wout]^T + biases ;
//                   hs computed in-CTA at K-chunk 24 (spin on mid counter)
// --------------------------------------------------------------------------
constexpr int G2_STG = 20480;
constexpr int G2_BI  = 4 * G2_STG;            // 81920: bias
constexpr int G2TOTAL = G2_BI + 512;          // 82432
constexpr int NKT = 25;
constexpr int SCAN_BLKS = 72;

__global__ void __launch_bounds__(256, 2) k_main(const float* __restrict__ bout,
                                                 const float* __restrict__ bskip,
                                                 float* __restrict__ y) {
    extern __shared__ char smem[];
    __shared__ __half sPp[CHUNK * 256];       // 16 KB static: fp16 Ppow (gemm2 role)
    int tid = threadIdx.x;
    int bid = blockIdx.x;

    if (bid < 64) {
        // ---- local scan role: 16 tasks (chunks) per block ----
        int task = bid * 16 + (tid >> 4);
        int n = tid & 15;
        float Trow[16];
#pragma unroll
        for (int m = 0; m < 16; m++) Trow[m] = d_Ppow[n * 16 + m];
        float* g = d_gu + (size_t)task * CHUNK * NST;
        float h = 0.f;
        float nxt = g[n];
        for (int j = 0; j < CHUNK; j++) {
            float curv = nxt;
            if (j + 1 < CHUNK) nxt = g[(j + 1) * NST + n];
            float hn = curv;
#pragma unroll
            for (int m = 0; m < 16; m++)
                hn += Trow[m] * __shfl_sync(0xffffffffu, h, m, 16);
            h = hn;
            g[j * NST + n] = h;
        }
        d_lend[task * NST + n] = h;
        __threadfence();
        __syncthreads();
        if (tid == 0) atomicAdd(&d_cnt_local, 1);
        return;
    }

    if (bid < SCAN_BLKS) {
        // ---- mid scan role: one batch per block ----
        int b = bid - 64;
        float4* buf0 = (float4*)smem;                 // 8 KB
        float4* buf1 = (float4*)(smem + 8192);        // 8 KB
        float*  Qs   = (float*)(smem + 16384);        // 7 KB
        for (int i = tid; i < 7 * 256; i += 256) Qs[i] = d_Qsq[i];
        // wait for all local blocks
        if (tid == 0) { while (((volatile int*)&d_cnt_local)[0] < 64) {} }
        __syncthreads();
        __threadfence();
        for (int u = tid; u < 512; u += 256)
            buf0[u] = ((const float4*)(d_lend + b * 2048))[u];
        __syncthreads();
        float4* src = buf0;
        float4* dst = buf1;
#pragma unroll
        for (int t = 0; t < 7; t++) {
            int o = 1 << t;
            const float4* Q4 = (const float4*)(Qs + t * 256);
            for (int u = tid; u < 512; u += 256) {
                int k = u >> 2, q = u & 3;
                float4 v = src[u];
                if (k >= o) {
                    const float4* sp = src + ((k - o) << 2);
                    float4 s0 = sp[0], s1 = sp[1], s2 = sp[2], s3 = sp[3];
#pragma unroll
                    for (int e = 0; e < 4; e++) {
                        int n = q * 4 + e;
                        float a = dot4(Q4[n * 4], s0) + dot4(Q4[n * 4 + 1], s1)
                                + dot4(Q4[n * 4 + 2], s2) + dot4(Q4[n * 4 + 3], s3);
                        if (e == 0) v.x += a; else if (e == 1) v.y += a;
                        else if (e == 2) v.z += a; else v.w += a;
                    }
                }
                dst[u] = v;
            }
            __syncthreads();
            float4* tmp = src; src = dst; dst = tmp;
        }
        for (int u = tid; u < 512; u += 256) {
            int k = u >> 2, q = u & 3;
            float4 out = (k == 0) ? make_float4(0.f, 0.f, 0.f, 0.f)
                                  : src[((k - 1) << 2) + q];
            ((float4*)(d_hstart + (size_t)b * NCHUNK * NST))[u] = out;
        }
        __threadfence();
        __syncthreads();
        if (tid == 0) atomicAdd(&d_cnt_mid, 1);
        return;
    }

    // ---- GEMM2 role ----
    int gid = bid - SCAN_BLKS;
    int mt = gid / 6, nt = gid % 6;
    uint32_t sb = smem_u32(smem);
    int w = tid >> 5, l = tid & 31;
    int mw = w >> 1, nw = w & 1;

    float* sBias = (float*)(smem + G2_BI);
    if (tid < 128) sBias[tid] = bout[nt * 128 + tid] + bskip[nt * 128 + tid];

    const __half* Asrc = d_xh + (size_t)mt * 128 * DIM;
    const __half* Bsrc = d_wsk + (size_t)nt * 128 * DIM;
    const __half* Bwo  = d_woh + (size_t)nt * 128 * NST;

    auto load_stage = [&](int kc) {
        uint32_t Ad = sb + (kc & 3) * G2_STG;
        uint32_t Bd = Ad + 10240;
        if (kc < 24) {
#pragma unroll
            for (int q = 0; q < 2; q++) {
                int s = tid + q * 256;
                int row = s >> 2, cs = s & 3;
                cpa16(Ad + (row * AST + cs * 8) * 2, Asrc + (size_t)row * DIM + kc * 32 + cs * 8);
                cpa16(Bd + (row * AST + cs * 8) * 2, Bsrc + (size_t)row * DIM + kc * 32 + cs * 8);
            }
        } else {
            // B side only: Wout cols 0..15 + zero cols 16..31. A side computed later.
#pragma unroll
            for (int q = 0; q < 2; q++) {
                int s = tid + q * 256;
                int row = s >> 2, cs = s & 3;
                if (cs < 2) {
                    cpa16(Bd + (row * AST + cs * 8) * 2, Bwo + row * NST + cs * 8);
                } else {
                    *(uint4*)(smem + (kc & 3) * G2_STG + 10240 + (row * AST + cs * 8) * 2) =
                        make_uint4(0u, 0u, 0u, 0u);
                }
            }
        }
    };

    float c[2][8][4];
#pragma unroll
    for (int i = 0; i < 2; i++)
#pragma unroll
        for (int j = 0; j < 8; j++)
#pragma unroll
            for (int e = 0; e < 4; e++) c[i][j][e] = 0.f;

    load_stage(0); cpa_commit();
    load_stage(1); cpa_commit();

    for (int kc = 0; kc < NKT; kc++) {
        if (kc + 2 < NKT) load_stage(kc + 2);
        cpa_commit();
        cpa_wait2();
        __syncthreads();

        if (kc == 24) {
            // wait for mid scan, then compute hs tile into stage-0 A
            if (tid == 0) { while (((volatile int*)&d_cnt_mid)[0] < 8) {} }
            __syncthreads();
            __threadfence();
            for (int i = tid; i < 1024; i += 256)
                ((uint4*)sPp)[i] = ((const uint4*)d_pph)[i];
            __syncthreads();

            int r_local = tid >> 1, hf = tid & 1;
            int rr = mt * 128 + r_local;
            int b2 = rr >> 12;
            int kk = (rr & 4095) >> 5;
            int jj = rr & 31;
            const float4* s4 = (const float4*)(d_hstart + (size_t)(b2 * NCHUNK + kk) * NST);
            float4 sv0 = s4[0], sv1 = s4[1], sv2 = s4[2], sv3 = s4[3];
            float sarr[16] = {sv0.x, sv0.y, sv0.z, sv0.w, sv1.x, sv1.y, sv1.z, sv1.w,
                              sv2.x, sv2.y, sv2.z, sv2.w, sv3.x, sv3.y, sv3.z, sv3.w};
            const float4* g4 = (const float4*)(d_gu + (size_t)rr * 16 + hf * 8);
            float4 ga = g4[0], gb = g4[1];
            float accv[8] = {ga.x, ga.y, ga.z, ga.w, gb.x, gb.y, gb.z, gb.w};
#pragma unroll
            for (int e = 0; e < 8; e++) {
                int n = hf * 8 + e;
                const __half2* pp = (const __half2*)(sPp + jj * 256 + n * 16);
#pragma unroll
                for (int q = 0; q < 8; q++) {
                    float2 pf = __half22float2(pp[q]);
                    accv[e] += pf.x * sarr[2 * q] + pf.y * sarr[2 * q + 1];
                }
            }
            __half2 h01 = __floats2half2_rn(accv[0], accv[1]);
            __half2 h23 = __floats2half2_rn(accv[2], accv[3]);
            __half2 h45 = __floats2half2_rn(accv[4], accv[5]);
            __half2 h67 = __floats2half2_rn(accv[6], accv[7]);
            char* Ad0 = smem + 0 * G2_STG;      // stage (24&3)=0
            *(uint4*)(Ad0 + (r_local * AST + hf * 8) * 2) =
                make_uint4(*(uint32_t*)&h01, *(uint32_t*)&h23,
                           *(uint32_t*)&h45, *(uint32_t*)&h67);
            *(uint4*)(Ad0 + (r_local * AST + 16 + hf * 8) * 2) =
                make_uint4(0u, 0u, 0u, 0u);
            __syncthreads();
        }

        uint32_t Ab = sb + (kc & 3) * G2_STG;
        uint32_t Bb = Ab + 10240;
#pragma unroll
        for (int ks = 0; ks < 2; ks++) {
            uint32_t a[2][4];
#pragma unroll
            for (int m2 = 0; m2 < 2; m2++)
                ldm4(a[m2], Ab + ((mw * 32 + m2 * 16 + (l & 15)) * AST + ks * 16 + (l >> 4) * 8) * 2);
            uint32_t bf[4][4];
#pragma unroll
            for (int i = 0; i < 4; i++)
                ldm4(bf[i], Bb + ((nw * 64 + i * 16 + (l & 15)) * AST + ks * 16 + (l >> 4) * 8) * 2);
#pragma unroll
            for (int m2 = 0; m2 < 2; m2++)
#pragma unroll
                for (int n2 = 0; n2 < 8; n2++)
                    mma16816(c[m2][n2], a[m2], bf[n2 >> 1][n2 & 1], bf[n2 >> 1][(n2 & 1) + 2]);
        }
    }

    int g = l >> 2, t2 = (l & 3) * 2;
#pragma unroll
    for (int m2 = 0; m2 < 2; m2++) {
#pragma unroll
        for (int h = 0; h < 2; h++) {
            int r = mt * 128 + mw * 32 + m2 * 16 + h * 8 + g;
            float* yb = y + (size_t)r * DIM + nt * 128;
#pragma unroll
            for (int n2 = 0; n2 < 8; n2++) {
                int col = nw * 64 + n2 * 8 + t2;
                float2 v = make_float2(c[m2][n2][2 * h]     + sBias[col],
                                       c[m2][n2][2 * h + 1] + sBias[col + 1]);
                *(float2*)(yb + col) = v;
            }
        }
    }
}

// --------------------------------------------------------------------------
extern "C" void kernel_launch(void* const* d_in, const int* in_sizes, int n_in,
                              void* d_out, int out_size) {
    (void)in_sizes; (void)n_in; (void)out_size;
    const float* x      = (const float*)d_in[0];
    const float* a_log  = (const float*)d_in[1];
    const float* U      = (const float*)d_in[2];
    const float* V      = (const float*)d_in[3];
    const float* Win    = (const float*)d_in[4];
    const float* bin    = (const float*)d_in[5];
    const float* Wgate  = (const float*)d_in[6];
    const float* bgate  = (const float*)d_in[7];
    const float* Wout   = (const float*)d_in[8];
    const float* bout   = (const float*)d_in[9];
    const float* Wskip  = (const float*)d_in[10];
    const float* bskip  = (const float*)d_in[11];
    float* y = (float*)d_out;

    cudaFuncSetAttribute(k_gemm1, cudaFuncAttributeMaxDynamicSharedMemorySize, G1TOTAL);
    cudaFuncSetAttribute(k_main,  cudaFuncAttributeMaxDynamicSharedMemorySize, G2TOTAL);

    k_gemm1<<<G1_GEMM_BLKS + G1_PREP_BLKS, 256, G1TOTAL>>>(
        x, Win, Wgate, bin, bgate, a_log, U, V, Wskip, Wout);
    k_main<<<SCAN_BLKS + 6 * 256, 256, G2TOTAL>>>(bout, bskip, y);
}